// round 2
// baseline (speedup 1.0000x reference)
#include <cuda_runtime.h>
#include <cuda_bf16.h>

#define TT 2048
#define BB 64
#define GG 192
#define OUT_MAIN 33554432

typedef unsigned long long ull;

// ---------------- device scratch (no cudaMalloc allowed) ----------------
__device__ float g_gi[(size_t)TT * BB * 768];          // ~403 MB input-side preactivations
__device__ ulonglong2 g_wihA[64 * 96];                 // {(r pair),(i pair)} per (u, col-pair)
__device__ ulonglong2 g_wihB[64 * 96];                 // {(j pair),(k pair)}
__device__ ulonglong2 g_whhA[64 * 96];
__device__ ulonglong2 g_whhB[64 * 96];

// ---------------- f32x2 helpers ----------------
__device__ __forceinline__ ull pk2(float a, float b) {
    ull r; asm("mov.b64 %0, {%1,%2};" : "=l"(r) : "f"(a), "f"(b)); return r;
}
__device__ __forceinline__ float2 upk2(ull v) {
    float2 r; asm("mov.b64 {%0,%1}, %2;" : "=f"(r.x), "=f"(r.y) : "l"(v)); return r;
}
#define FMA2(acc, a, b) asm("fma.rn.f32x2 %0, %1, %2, %0;" : "+l"(acc) : "l"(a), "l"(b))

// Full quaternion (Hamilton) product contribution for one u and one column
// pair: 16 packed FMAs. P/N accumulator split avoids operand negation.
//  out_r = hr*r - (hi*i + hj*j + hk*k)
//  out_i = hr*i + hi*r + hk*j - hj*k
//  out_j = hr*j + hi*k + hj*r - hk*i
//  out_k = hr*k + hj*i + hk*r - hi*j
#define QFMA16(hr2,hi2,hj2,hk2, wr2,wi2,wj2,wk2, Pr,Nr,Pi,Ni,Pj,Nj,Pk,Nk) do { \
    FMA2(Pr,hr2,wr2); FMA2(Nr,hi2,wi2); FMA2(Nr,hj2,wj2); FMA2(Nr,hk2,wk2);    \
    FMA2(Pi,hr2,wi2); FMA2(Pi,hi2,wr2); FMA2(Pi,hk2,wj2); FMA2(Ni,hj2,wk2);    \
    FMA2(Pj,hr2,wj2); FMA2(Pj,hi2,wk2); FMA2(Pj,hj2,wr2); FMA2(Nj,hk2,wi2);    \
    FMA2(Pk,hr2,wk2); FMA2(Pk,hj2,wi2); FMA2(Pk,hk2,wr2); FMA2(Nk,hi2,wj2);    \
} while (0)

__device__ __forceinline__ float sig_f(float x) {
    return 1.0f / (1.0f + __expf(-x));
}
__device__ __forceinline__ float tanh_f(float x) {
    float e = __expf(2.0f * x);
    return 1.0f - 2.0f / (e + 1.0f);
}

// ---------------- weight packing ----------------
__global__ void qrn_prep(const float* __restrict__ wihr, const float* __restrict__ wihi,
                         const float* __restrict__ wihj, const float* __restrict__ wihk,
                         const float* __restrict__ whhr, const float* __restrict__ whhi,
                         const float* __restrict__ whhj, const float* __restrict__ whhk) {
    int idx = blockIdx.x * blockDim.x + threadIdx.x;
    if (idx >= 64 * 96) return;
    int u = idx / 96, jp = idx % 96;
    int c0 = u * GG + 2 * jp;
    ulonglong2 a, bv;
    a.x  = pk2(wihr[c0], wihr[c0 + 1]); a.y  = pk2(wihi[c0], wihi[c0 + 1]);
    bv.x = pk2(wihj[c0], wihj[c0 + 1]); bv.y = pk2(wihk[c0], wihk[c0 + 1]);
    g_wihA[idx] = a; g_wihB[idx] = bv;
    a.x  = pk2(whhr[c0], whhr[c0 + 1]); a.y  = pk2(whhi[c0], whhi[c0 + 1]);
    bv.x = pk2(whhj[c0], whhj[c0 + 1]); bv.y = pk2(whhk[c0], whhk[c0 + 1]);
    g_whhA[idx] = a; g_whhB[idx] = bv;
}

// ---------------- phase 1: gi = x @ W_ih + b_ih ----------------
// Persistent 148 CTAs; weights resident in smem; 16-row x tiles.
// 384 threads = 96 column-pairs x 4 row-groups (4 rows each).
#define GEMM_SMEM (98304 * 2 + 16384)
__global__ __launch_bounds__(384, 1) void qrn_gemm(const float* __restrict__ x,
                                                   const float* __restrict__ bih) {
    extern __shared__ char smem[];
    ulonglong2* swA = (ulonglong2*)smem;
    ulonglong2* swB = (ulonglong2*)(smem + 98304);
    float* xs = (float*)(smem + 196608);
    int t = threadIdx.x;
    for (int i = t; i < 6144; i += 384) { swA[i] = g_wihA[i]; swB[i] = g_wihB[i]; }
    int jp = t % 96, rg = t / 96;
    float2 bias2[4];
#pragma unroll
    for (int q = 0; q < 4; ++q) bias2[q] = *(const float2*)(bih + q * GG + 2 * jp);

    for (int tile = blockIdx.x; tile < 8192; tile += gridDim.x) {
        __syncthreads();
        const float4* xt4 = (const float4*)(x + (size_t)tile * 4096);
        float4* xs4 = (float4*)xs;
        for (int i = t; i < 1024; i += 384) xs4[i] = xt4[i];
        __syncthreads();

        ull acc[4][8];
#pragma unroll
        for (int rr = 0; rr < 4; ++rr)
#pragma unroll
            for (int k = 0; k < 8; ++k) acc[rr][k] = 0ull;

#pragma unroll 4
        for (int u = 0; u < 64; ++u) {
            ulonglong2 wA = swA[u * 96 + jp];
            ulonglong2 wB = swB[u * 96 + jp];
#pragma unroll
            for (int rr = 0; rr < 4; ++rr) {
                const float* xr = xs + (rg * 4 + rr) * 256 + u;
                float hr = xr[0], hi = xr[64], hj = xr[128], hk = xr[192];
                ull hr2 = pk2(hr, hr), hi2 = pk2(hi, hi);
                ull hj2 = pk2(hj, hj), hk2 = pk2(hk, hk);
                QFMA16(hr2, hi2, hj2, hk2, wA.x, wA.y, wB.x, wB.y,
                       acc[rr][0], acc[rr][1], acc[rr][2], acc[rr][3],
                       acc[rr][4], acc[rr][5], acc[rr][6], acc[rr][7]);
            }
        }

#pragma unroll
        for (int rr = 0; rr < 4; ++rr) {
            float* go = g_gi + ((size_t)tile * 16 + rg * 4 + rr) * 768;
#pragma unroll
            for (int q = 0; q < 4; ++q) {
                float2 p = upk2(acc[rr][2 * q]);
                float2 n = upk2(acc[rr][2 * q + 1]);
                float2 o;
                o.x = p.x - n.x + bias2[q].x;
                o.y = p.y - n.y + bias2[q].y;
                *(float2*)(go + q * GG + 2 * jp) = o;
            }
        }
    }
}

// ---------------- phase 2: recurrence, one CTA per batch element ----------------
// 384 threads = 96 column-pairs x 4 u-partitions (16 u each).
// W_hh slice lives entirely in registers (128 f32/thread).
__global__ __launch_bounds__(384, 1) void qrn_recur(const float* __restrict__ hx,
                                                    const float* __restrict__ bhh,
                                                    float* __restrict__ out, int out_size) {
    __shared__ __align__(16) float4 h4v[64];           // (r,i,j,k) per hidden unit u
    __shared__ __align__(16) float red[4 * 768];       // partition partials
    __shared__ __align__(16) float4 gis4[2 * 192];     // double-buffered gi_t
    float* gis = (float*)gis4;

    int t = threadIdx.x, b = blockIdx.x;
    int jp = t % 96, up = t / 96, ub = up * 16;

    // register-resident weights
    ulonglong2 wAr[16], wBr[16];
#pragma unroll
    for (int uu = 0; uu < 16; ++uu) {
        wAr[uu] = g_whhA[(ub + uu) * 96 + jp];
        wBr[uu] = g_whhB[(ub + uu) * 96 + jp];
    }

    float hcur = 0.f, bh0 = 0.f, bh1 = 0.f, bh2 = 0.f;
    int q = 0, u = 0;
    if (t < 256) {
        q = t >> 6; u = t & 63;
        hcur = hx[b * 256 + t];
        ((float*)h4v)[u * 4 + q] = hcur;
        bh0 = bhh[q * GG + u];
        bh1 = bhh[q * GG + 64 + u];
        bh2 = bhh[q * GG + 128 + u];
    }
    if (t < 192)
        *(float4*)(gis + 4 * t) = *(const float4*)(g_gi + (size_t)b * 768 + 4 * t);
    __syncthreads();

#pragma unroll 1
    for (int step = 0; step < TT; ++step) {
        int cb = step & 1;
        bool pf = (t < 192) && (step < TT - 1);
        float4 gnext = make_float4(0.f, 0.f, 0.f, 0.f);
        if (pf)
            gnext = *(const float4*)(g_gi + ((size_t)(step + 1) * BB + b) * 768 + 4 * t);

        ull Pr = 0, Nr = 0, Pi = 0, Ni = 0, Pj = 0, Nj = 0, Pk = 0, Nk = 0;
#pragma unroll
        for (int uu = 0; uu < 16; ++uu) {
            float4 h = h4v[ub + uu];
            ull hr2 = pk2(h.x, h.x), hi2 = pk2(h.y, h.y);
            ull hj2 = pk2(h.z, h.z), hk2 = pk2(h.w, h.w);
            QFMA16(hr2, hi2, hj2, hk2, wAr[uu].x, wAr[uu].y, wBr[uu].x, wBr[uu].y,
                   Pr, Nr, Pi, Ni, Pj, Nj, Pk, Nk);
        }
        {
            float2 pr = upk2(Pr), nr = upk2(Nr), pi = upk2(Pi), ni = upk2(Ni);
            float2 pj = upk2(Pj), nj = upk2(Nj), pk = upk2(Pk), nk = upk2(Nk);
            float* rb = red + up * 768 + 2 * jp;
            float2 v;
            v.x = pr.x - nr.x; v.y = pr.y - nr.y; *(float2*)(rb)       = v;
            v.x = pi.x - ni.x; v.y = pi.y - ni.y; *(float2*)(rb + 192) = v;
            v.x = pj.x - nj.x; v.y = pj.y - nj.y; *(float2*)(rb + 384) = v;
            v.x = pk.x - nk.x; v.y = pk.y - nk.y; *(float2*)(rb + 576) = v;
        }
        if (pf)
            *(float4*)(gis + (cb ^ 1) * 768 + 4 * t) = gnext;
        __syncthreads();

        if (t < 256) {
            int o0 = q * GG + u;
            float gh0 = red[o0]        + red[768 + o0]        + red[1536 + o0]        + red[2304 + o0];
            float gh1 = red[o0 + 64]   + red[768 + o0 + 64]   + red[1536 + o0 + 64]   + red[2304 + o0 + 64];
            float gh2 = red[o0 + 128]  + red[768 + o0 + 128]  + red[1536 + o0 + 128]  + red[2304 + o0 + 128];
            const float* gc = gis + cb * 768;
            float rg_ = sig_f(gc[o0] + gh0 + bh0);
            float zg  = sig_f(gc[o0 + 64] + gh1 + bh1);
            float ng  = tanh_f(gc[o0 + 128] + rg_ * (gh2 + bh2));
            hcur = ng + zg * (hcur - ng);
            ((float*)h4v)[u * 4 + q] = hcur;
            out[((size_t)step * BB + b) * 256 + t] = hcur;
        }
        __syncthreads();
    }

    if (t < 256 && out_size >= OUT_MAIN + BB * 256)
        out[OUT_MAIN + b * 256 + t] = hcur;
}

extern "C" void kernel_launch(void* const* d_in, const int* in_sizes, int n_in,
                              void* d_out, int out_size) {
    const float* x    = (const float*)d_in[0];
    const float* hx   = (const float*)d_in[1];
    const float* wihr = (const float*)d_in[2];
    const float* wihi = (const float*)d_in[3];
    const float* wihj = (const float*)d_in[4];
    const float* wihk = (const float*)d_in[5];
    const float* whhr = (const float*)d_in[6];
    const float* whhi = (const float*)d_in[7];
    const float* whhj = (const float*)d_in[8];
    const float* whhk = (const float*)d_in[9];
    const float* bih  = (const float*)d_in[10];
    const float* bhh  = (const float*)d_in[11];
    float* out = (float*)d_out;

    qrn_prep<<<24, 256>>>(wihr, wihi, wihj, wihk, whhr, whhi, whhj, whhk);

    cudaFuncSetAttribute(qrn_gemm, cudaFuncAttributeMaxDynamicSharedMemorySize, GEMM_SMEM);
    qrn_gemm<<<148, 384, GEMM_SMEM>>>(x, bih);

    qrn_recur<<<64, 384>>>(hx, bhh, out, out_size);
}

// round 3
// speedup vs baseline: 1.0166x; 1.0166x over previous
#include <cuda_runtime.h>
#include <cuda_bf16.h>

#define TT 2048
#define BB 64
#define GG 192
#define OUT_MAIN 33554432
#define NCONS 64
#define NPROD 84
#define NTILE 8192

typedef unsigned long long ull;

// ---------------- device scratch (no cudaMalloc allowed) ----------------
__device__ float g_gi[(size_t)TT * BB * 768];          // input-side preactivations
__device__ ulonglong2 g_wihA[64 * 96];                 // {(r pair),(i pair)} per (u, col-pair)
__device__ ulonglong2 g_wihB[64 * 96];                 // {(j pair),(k pair)}
__device__ ulonglong2 g_whhA[64 * 96];
__device__ ulonglong2 g_whhB[64 * 96];
__device__ unsigned   g_tdone[TT];                     // tiles completed per timestep (target 4)

// ---------------- f32x2 helpers ----------------
__device__ __forceinline__ ull pk2(float a, float b) {
    ull r; asm("mov.b64 %0, {%1,%2};" : "=l"(r) : "f"(a), "f"(b)); return r;
}
__device__ __forceinline__ float2 upk2(ull v) {
    float2 r; asm("mov.b64 {%0,%1}, %2;" : "=f"(r.x), "=f"(r.y) : "l"(v)); return r;
}
#define FMA2(acc, a, b) asm("fma.rn.f32x2 %0, %1, %2, %0;" : "+l"(acc) : "l"(a), "l"(b))

// Full quaternion (Hamilton) product contribution for one u and one column
// pair: 16 packed FMAs. P/N accumulator split avoids operand negation.
#define QFMA16(hr2,hi2,hj2,hk2, wr2,wi2,wj2,wk2, Pr,Nr,Pi,Ni,Pj,Nj,Pk,Nk) do { \
    FMA2(Pr,hr2,wr2); FMA2(Nr,hi2,wi2); FMA2(Nr,hj2,wj2); FMA2(Nr,hk2,wk2);    \
    FMA2(Pi,hr2,wi2); FMA2(Pi,hi2,wr2); FMA2(Pi,hk2,wj2); FMA2(Ni,hj2,wk2);    \
    FMA2(Pj,hr2,wj2); FMA2(Pj,hi2,wk2); FMA2(Pj,hj2,wr2); FMA2(Nj,hk2,wi2);    \
    FMA2(Pk,hr2,wk2); FMA2(Pk,hj2,wi2); FMA2(Pk,hk2,wr2); FMA2(Nk,hi2,wj2);    \
} while (0)

__device__ __forceinline__ float sig_f(float x) {
    return 1.0f / (1.0f + __expf(-x));
}
__device__ __forceinline__ float tanh_f(float x) {
    float e = __expf(2.0f * x);
    return 1.0f - 2.0f / (e + 1.0f);
}

// ---------------- weight packing + flag reset ----------------
__global__ void qrn_prep(const float* __restrict__ wihr, const float* __restrict__ wihi,
                         const float* __restrict__ wihj, const float* __restrict__ wihk,
                         const float* __restrict__ whhr, const float* __restrict__ whhi,
                         const float* __restrict__ whhj, const float* __restrict__ whhk) {
    int idx = blockIdx.x * blockDim.x + threadIdx.x;
    if (idx < TT) g_tdone[idx] = 0u;                  // reset producer/consumer flags
    if (idx >= 64 * 96) return;
    int u = idx / 96, jp = idx % 96;
    int c0 = u * GG + 2 * jp;
    ulonglong2 a, bv;
    a.x  = pk2(wihr[c0], wihr[c0 + 1]); a.y  = pk2(wihi[c0], wihi[c0 + 1]);
    bv.x = pk2(wihj[c0], wihj[c0 + 1]); bv.y = pk2(wihk[c0], wihk[c0 + 1]);
    g_wihA[idx] = a; g_wihB[idx] = bv;
    a.x  = pk2(whhr[c0], whhr[c0 + 1]); a.y  = pk2(whhi[c0], whhi[c0 + 1]);
    bv.x = pk2(whhj[c0], whhj[c0 + 1]); bv.y = pk2(whhk[c0], whhk[c0 + 1]);
    g_whhA[idx] = a; g_whhB[idx] = bv;
}

// ---------------- fused kernel ----------------
// CTAs [0,64): recurrence consumers, one per batch element.
// CTAs [64,148): gi-GEMM producers; tiles ascend in t; per-t done counter.
// All 148 CTAs co-resident (1 CTA/SM at 212KB smem) -> spin sync is safe.
#define FUSED_SMEM (196608 + 16384)

__global__ __launch_bounds__(384, 1) void qrn_fused(const float* __restrict__ x,
                                                    const float* __restrict__ bih,
                                                    const float* __restrict__ hx,
                                                    const float* __restrict__ bhh,
                                                    float* __restrict__ out, int out_size) {
    extern __shared__ char smem[];
    int t = threadIdx.x;

    if (blockIdx.x >= NCONS) {
        // ================= producer: gi = x @ W_ih + b_ih =================
        ulonglong2* swA = (ulonglong2*)smem;
        ulonglong2* swB = (ulonglong2*)(smem + 98304);
        float* xs = (float*)(smem + 196608);
        for (int i = t; i < 6144; i += 384) { swA[i] = g_wihA[i]; swB[i] = g_wihB[i]; }
        int jp = t % 96, rg = t / 96;
        float2 bias2[4];
#pragma unroll
        for (int q = 0; q < 4; ++q) bias2[q] = *(const float2*)(bih + q * GG + 2 * jp);

        int pid = (int)blockIdx.x - NCONS;
        for (int tile = pid; tile < NTILE; tile += NPROD) {
            __syncthreads();
            const float4* xt4 = (const float4*)(x + (size_t)tile * 4096);
            float4* xs4 = (float4*)xs;
            for (int i = t; i < 1024; i += 384) xs4[i] = xt4[i];
            __syncthreads();

            ull acc[4][8];
#pragma unroll
            for (int rr = 0; rr < 4; ++rr)
#pragma unroll
                for (int k = 0; k < 8; ++k) acc[rr][k] = 0ull;

#pragma unroll 4
            for (int u = 0; u < 64; ++u) {
                ulonglong2 wA = swA[u * 96 + jp];
                ulonglong2 wB = swB[u * 96 + jp];
#pragma unroll
                for (int rr = 0; rr < 4; ++rr) {
                    const float* xr = xs + (rg * 4 + rr) * 256 + u;
                    float hr = xr[0], hi = xr[64], hj = xr[128], hk = xr[192];
                    ull hr2 = pk2(hr, hr), hi2 = pk2(hi, hi);
                    ull hj2 = pk2(hj, hj), hk2 = pk2(hk, hk);
                    QFMA16(hr2, hi2, hj2, hk2, wA.x, wA.y, wB.x, wB.y,
                           acc[rr][0], acc[rr][1], acc[rr][2], acc[rr][3],
                           acc[rr][4], acc[rr][5], acc[rr][6], acc[rr][7]);
                }
            }

#pragma unroll
            for (int rr = 0; rr < 4; ++rr) {
                float* go = g_gi + ((size_t)tile * 16 + rg * 4 + rr) * 768;
#pragma unroll
                for (int q = 0; q < 4; ++q) {
                    float2 p = upk2(acc[rr][2 * q]);
                    float2 n = upk2(acc[rr][2 * q + 1]);
                    float2 o;
                    o.x = p.x - n.x + bias2[q].x;
                    o.y = p.y - n.y + bias2[q].y;
                    *(float2*)(go + q * GG + 2 * jp) = o;
                }
            }
            __threadfence();               // release: gi data visible before flag bump
            __syncthreads();               // all threads' stores done
            if (t == 0) atomicAdd(&g_tdone[tile >> 2], 1u);
        }
        return;
    }

    // ================= consumer: recurrence, one CTA per batch =================
    float4* h4v = (float4*)smem;                       // 1KB: (r,i,j,k) per hidden unit
    float*  red = (float*)(smem + 1024);               // 12KB: partition partials
    float*  gis = (float*)(smem + 13312);              // 6KB: double-buffered gi_t

    int b = blockIdx.x;
    int jp = t % 96, up = t / 96, ub = up * 16;

    // register-resident W_hh slice
    ulonglong2 wAr[16], wBr[16];
#pragma unroll
    for (int uu = 0; uu < 16; ++uu) {
        wAr[uu] = g_whhA[(ub + uu) * 96 + jp];
        wBr[uu] = g_whhB[(ub + uu) * 96 + jp];
    }

    // wait for gi[t=0] and gi[t=1]
    if (t == 0) {
        while (atomicAdd(&g_tdone[0], 0u) < 4u) { }
        while (atomicAdd(&g_tdone[1], 0u) < 4u) { }
    }
    __syncthreads();
    __threadfence();

    float hcur = 0.f, bh0 = 0.f, bh1 = 0.f, bh2 = 0.f;
    int q = 0, u = 0;
    if (t < 256) {
        q = t >> 6; u = t & 63;
        hcur = hx[b * 256 + t];
        ((float*)h4v)[u * 4 + q] = hcur;
        bh0 = bhh[q * GG + u];
        bh1 = bhh[q * GG + 64 + u];
        bh2 = bhh[q * GG + 128 + u];
    }
    if (t < 192)
        *(float4*)(gis + 4 * t) = *(const float4*)(g_gi + (size_t)b * 768 + 4 * t);
    __syncthreads();

#pragma unroll 1
    for (int step = 0; step < TT; ++step) {
        int cb = step & 1;
        bool pf = (t < 192) && (step < TT - 1);
        float4 gnext = make_float4(0.f, 0.f, 0.f, 0.f);
        if (pf)   // gi[step+1] readiness guaranteed by spin in step-1's tail (or init)
            gnext = *(const float4*)(g_gi + ((size_t)(step + 1) * BB + b) * 768 + 4 * t);

        ull Pr = 0, Nr = 0, Pi = 0, Ni = 0, Pj = 0, Nj = 0, Pk = 0, Nk = 0;
#pragma unroll
        for (int uu = 0; uu < 16; ++uu) {
            float4 h = h4v[ub + uu];
            ull hr2 = pk2(h.x, h.x), hi2 = pk2(h.y, h.y);
            ull hj2 = pk2(h.z, h.z), hk2 = pk2(h.w, h.w);
            QFMA16(hr2, hi2, hj2, hk2, wAr[uu].x, wAr[uu].y, wBr[uu].x, wBr[uu].y,
                   Pr, Nr, Pi, Ni, Pj, Nj, Pk, Nk);
        }
        {
            float2 pr = upk2(Pr), nr = upk2(Nr), pi = upk2(Pi), ni = upk2(Ni);
            float2 pj = upk2(Pj), nj = upk2(Nj), pk = upk2(Pk), nk = upk2(Nk);
            float* rb = red + up * 768 + 2 * jp;
            float2 v;
            v.x = pr.x - nr.x; v.y = pr.y - nr.y; *(float2*)(rb)       = v;
            v.x = pi.x - ni.x; v.y = pi.y - ni.y; *(float2*)(rb + 192) = v;
            v.x = pj.x - nj.x; v.y = pj.y - nj.y; *(float2*)(rb + 384) = v;
            v.x = pk.x - nk.x; v.y = pk.y - nk.y; *(float2*)(rb + 576) = v;
        }
        if (pf)
            *(float4*)(gis + (cb ^ 1) * 768 + 4 * t) = gnext;
        __syncthreads();

        if (t < 256) {
            int o0 = q * GG + u;
            float gh0 = red[o0]       + red[768 + o0]       + red[1536 + o0]       + red[2304 + o0];
            float gh1 = red[o0 + 64]  + red[768 + o0 + 64]  + red[1536 + o0 + 64]  + red[2304 + o0 + 64];
            float gh2 = red[o0 + 128] + red[768 + o0 + 128] + red[1536 + o0 + 128] + red[2304 + o0 + 128];
            const float* gc = gis + cb * 768;
            float rg_ = sig_f(gc[o0] + gh0 + bh0);
            float zg  = sig_f(gc[o0 + 64] + gh1 + bh1);
            float ng  = tanh_f(gc[o0 + 128] + rg_ * (gh2 + bh2));
            hcur = ng + zg * (hcur - ng);
            ((float*)h4v)[u * 4 + q] = hcur;
            out[((size_t)step * BB + b) * 256 + t] = hcur;
        } else if (t == 383) {
            // idle-lane spin: ensure gi[step+2] (prefetched next iteration) is ready
            int tt = step + 2;
            if (tt < TT) {
                while (atomicAdd(&g_tdone[tt], 0u) < 4u) { }
                __threadfence();
            }
        }
        __syncthreads();
    }

    if (t < 256 && out_size >= OUT_MAIN + BB * 256)
        out[OUT_MAIN + b * 256 + t] = hcur;
}

extern "C" void kernel_launch(void* const* d_in, const int* in_sizes, int n_in,
                              void* d_out, int out_size) {
    const float* x    = (const float*)d_in[0];
    const float* hx   = (const float*)d_in[1];
    const float* wihr = (const float*)d_in[2];
    const float* wihi = (const float*)d_in[3];
    const float* wihj = (const float*)d_in[4];
    const float* wihk = (const float*)d_in[5];
    const float* whhr = (const float*)d_in[6];
    const float* whhi = (const float*)d_in[7];
    const float* whhj = (const float*)d_in[8];
    const float* whhk = (const float*)d_in[9];
    const float* bih  = (const float*)d_in[10];
    const float* bhh  = (const float*)d_in[11];
    float* out = (float*)d_out;

    qrn_prep<<<24, 256>>>(wihr, wihi, wihj, wihk, whhr, whhi, whhj, whhk);

    cudaFuncSetAttribute(qrn_fused, cudaFuncAttributeMaxDynamicSharedMemorySize, FUSED_SMEM);
    qrn_fused<<<NCONS + NPROD, 384, FUSED_SMEM>>>(x, bih, hx, bhh, out, out_size);
}

// round 4
// speedup vs baseline: 1.0262x; 1.0094x over previous
#include <cuda_runtime.h>
#include <cuda_bf16.h>

#define TT 2048
#define BB 64
#define GG 192
#define OUT_MAIN 33554432
#define NCONS 64
#define NPROD 84
#define NTILE 8192

typedef unsigned long long ull;

// ---------------- device scratch (no cudaMalloc allowed) ----------------
__device__ float g_gi[(size_t)TT * BB * 768];          // input-side preactivations
__device__ ulonglong2 g_wihA[64 * 96];                 // {(r pair),(i pair)} per (u, col-pair)
__device__ ulonglong2 g_wihB[64 * 96];                 // {(j pair),(k pair)}
__device__ ulonglong2 g_whhA[64 * 96];
__device__ ulonglong2 g_whhB[64 * 96];
__device__ unsigned   g_tdone[TT];                     // tiles completed per timestep (target 4)

// ---------------- f32x2 helpers ----------------
__device__ __forceinline__ ull pk2(float a, float b) {
    ull r; asm("mov.b64 %0, {%1,%2};" : "=l"(r) : "f"(a), "f"(b)); return r;
}
__device__ __forceinline__ float2 upk2(ull v) {
    float2 r; asm("mov.b64 {%0,%1}, %2;" : "=f"(r.x), "=f"(r.y) : "l"(v)); return r;
}
#define FMA2(acc, a, b) asm("fma.rn.f32x2 %0, %1, %2, %0;" : "+l"(acc) : "l"(a), "l"(b))

// Full quaternion (Hamilton) product contribution for one u and one column
// pair: 16 packed FMAs. P/N accumulator split avoids operand negation.
#define QFMA16(hr2,hi2,hj2,hk2, wr2,wi2,wj2,wk2, Pr,Nr,Pi,Ni,Pj,Nj,Pk,Nk) do { \
    FMA2(Pr,hr2,wr2); FMA2(Nr,hi2,wi2); FMA2(Nr,hj2,wj2); FMA2(Nr,hk2,wk2);    \
    FMA2(Pi,hr2,wi2); FMA2(Pi,hi2,wr2); FMA2(Pi,hk2,wj2); FMA2(Ni,hj2,wk2);    \
    FMA2(Pj,hr2,wj2); FMA2(Pj,hi2,wk2); FMA2(Pj,hj2,wr2); FMA2(Nj,hk2,wi2);    \
    FMA2(Pk,hr2,wk2); FMA2(Pk,hj2,wi2); FMA2(Pk,hk2,wr2); FMA2(Nk,hi2,wj2);    \
} while (0)

__device__ __forceinline__ float sig_f(float x) {
    return 1.0f / (1.0f + __expf(-x));
}
__device__ __forceinline__ float tanh_f(float x) {
    float e = __expf(2.0f * x);
    return 1.0f - 2.0f / (e + 1.0f);
}

// ---------------- weight packing + flag reset ----------------
__global__ void qrn_prep(const float* __restrict__ wihr, const float* __restrict__ wihi,
                         const float* __restrict__ wihj, const float* __restrict__ wihk,
                         const float* __restrict__ whhr, const float* __restrict__ whhi,
                         const float* __restrict__ whhj, const float* __restrict__ whhk) {
    int idx = blockIdx.x * blockDim.x + threadIdx.x;
    if (idx < TT) g_tdone[idx] = 0u;                  // reset producer/consumer flags
    if (idx >= 64 * 96) return;
    int u = idx / 96, jp = idx % 96;
    int c0 = u * GG + 2 * jp;
    ulonglong2 a, bv;
    a.x  = pk2(wihr[c0], wihr[c0 + 1]); a.y  = pk2(wihi[c0], wihi[c0 + 1]);
    bv.x = pk2(wihj[c0], wihj[c0 + 1]); bv.y = pk2(wihk[c0], wihk[c0 + 1]);
    g_wihA[idx] = a; g_wihB[idx] = bv;
    a.x  = pk2(whhr[c0], whhr[c0 + 1]); a.y  = pk2(whhi[c0], whhi[c0 + 1]);
    bv.x = pk2(whhj[c0], whhj[c0 + 1]); bv.y = pk2(whhk[c0], whhk[c0 + 1]);
    g_whhA[idx] = a; g_whhB[idx] = bv;
}

// ---------------- fused kernel ----------------
// CTAs [0,64): recurrence consumers, one per batch element.
// CTAs [64,148): gi-GEMM producers; tiles ascend in t; per-t done counter.
// All 148 CTAs co-resident (1 CTA/SM at ~208KB smem) -> spin sync is safe.
#define FUSED_SMEM (196608 + 16384)

__global__ __launch_bounds__(384, 1) void qrn_fused(const float* __restrict__ x,
                                                    const float* __restrict__ bih,
                                                    const float* __restrict__ hx,
                                                    const float* __restrict__ bhh,
                                                    float* __restrict__ out, int out_size) {
    extern __shared__ char smem[];
    int t = threadIdx.x;

    if (blockIdx.x >= NCONS) {
        // ================= producer: gi = x @ W_ih + b_ih =================
        ulonglong2* swA = (ulonglong2*)smem;
        ulonglong2* swB = (ulonglong2*)(smem + 98304);
        float* xs = (float*)(smem + 196608);
        for (int i = t; i < 6144; i += 384) { swA[i] = g_wihA[i]; swB[i] = g_wihB[i]; }
        int jp = t % 96, rg = t / 96;
        float2 bias2[4];
#pragma unroll
        for (int q = 0; q < 4; ++q) bias2[q] = *(const float2*)(bih + q * GG + 2 * jp);

        int pid = (int)blockIdx.x - NCONS;
        for (int tile = pid; tile < NTILE; tile += NPROD) {
            __syncthreads();
            const float4* xt4 = (const float4*)(x + (size_t)tile * 4096);
            float4* xs4 = (float4*)xs;
            for (int i = t; i < 1024; i += 384) xs4[i] = xt4[i];
            __syncthreads();

            ull acc[4][8];
#pragma unroll
            for (int rr = 0; rr < 4; ++rr)
#pragma unroll
                for (int k = 0; k < 8; ++k) acc[rr][k] = 0ull;

#pragma unroll 4
            for (int u = 0; u < 64; ++u) {
                ulonglong2 wA = swA[u * 96 + jp];
                ulonglong2 wB = swB[u * 96 + jp];
#pragma unroll
                for (int rr = 0; rr < 4; ++rr) {
                    const float* xr = xs + (rg * 4 + rr) * 256 + u;
                    float hr = xr[0], hi = xr[64], hj = xr[128], hk = xr[192];
                    ull hr2 = pk2(hr, hr), hi2 = pk2(hi, hi);
                    ull hj2 = pk2(hj, hj), hk2 = pk2(hk, hk);
                    QFMA16(hr2, hi2, hj2, hk2, wA.x, wA.y, wB.x, wB.y,
                           acc[rr][0], acc[rr][1], acc[rr][2], acc[rr][3],
                           acc[rr][4], acc[rr][5], acc[rr][6], acc[rr][7]);
                }
            }

#pragma unroll
            for (int rr = 0; rr < 4; ++rr) {
                float* go = g_gi + ((size_t)tile * 16 + rg * 4 + rr) * 768;
#pragma unroll
                for (int q = 0; q < 4; ++q) {
                    float2 p = upk2(acc[rr][2 * q]);
                    float2 n = upk2(acc[rr][2 * q + 1]);
                    float2 o;
                    o.x = p.x - n.x + bias2[q].x;
                    o.y = p.y - n.y + bias2[q].y;
                    *(float2*)(go + q * GG + 2 * jp) = o;
                }
            }
            __threadfence();               // release: gi data visible before flag bump
            __syncthreads();               // all threads' stores done
            if (t == 0) atomicAdd(&g_tdone[tile >> 2], 1u);
        }
        return;
    }

    // ================= consumer: recurrence, one CTA per batch =================
    // smem: W_hh copy 192KB + red 12KB + h4dup 2KB  (regs stay ~50)
    ulonglong2* swA = (ulonglong2*)smem;                 // 96KB
    ulonglong2* swB = (ulonglong2*)(smem + 98304);       // 96KB
    float*  red   = (float*)(smem + 196608);             // 12KB: partition partials
    float*  h4dup = (float*)(smem + 208896);             // 2KB: {hr,hr,hi,hi,hj,hj,hk,hk}/u

    int b = blockIdx.x;
    int jp = t % 96, up = t / 96, ub = up * 16;

    for (int i = t; i < 6144; i += 384) { swA[i] = g_whhA[i]; swB[i] = g_whhB[i]; }

    float hcur = 0.f, bh0 = 0.f, bh1 = 0.f, bh2 = 0.f;
    int q = 0, u = 0, o0 = 0;
    if (t < 256) {
        q = t >> 6; u = t & 63; o0 = q * GG + u;
        hcur = hx[b * 256 + t];
        h4dup[u * 8 + 2 * q]     = hcur;
        h4dup[u * 8 + 2 * q + 1] = hcur;
        bh0 = bhh[o0];
        bh1 = bhh[o0 + 64];
        bh2 = bhh[o0 + 128];
    }

    // init sync: ensure gi[0..9] are produced
    if (t == 383) {
        for (int tt = 0; tt < 10; ++tt)
            while (atomicAdd(&g_tdone[tt], 0u) < 4u) { }
        __threadfence();
    }
    __syncthreads();

    // preload gi[0] into registers
    float gc0 = 0.f, gc1 = 0.f, gc2 = 0.f;
    if (t < 256) {
        const float* gp = g_gi + (size_t)b * 768 + o0;
        gc0 = gp[0]; gc1 = gp[64]; gc2 = gp[128];
    }

#pragma unroll 1
    for (int step = 0; step < TT; ++step) {
        // prefetch gi[step+1] into registers (full-step latency cover)
        float gn0 = 0.f, gn1 = 0.f, gn2 = 0.f;
        if (t < 256 && step + 1 < TT) {
            const float* gp = g_gi + ((size_t)(step + 1) * BB + b) * 768 + o0;
            gn0 = __ldcg(gp); gn1 = __ldcg(gp + 64); gn2 = __ldcg(gp + 128);
        }

        ull Pr = 0, Nr = 0, Pi = 0, Ni = 0, Pj = 0, Nj = 0, Pk = 0, Nk = 0;
#pragma unroll
        for (int uu = 0; uu < 16; ++uu) {
            int ui = ub + uu;
            ulonglong2 wA = swA[ui * 96 + jp];
            ulonglong2 wB = swB[ui * 96 + jp];
            ulonglong2 hA = *(ulonglong2*)(h4dup + ui * 8);       // {hr,hr,hi,hi}
            ulonglong2 hB = *(ulonglong2*)(h4dup + ui * 8 + 4);   // {hj,hj,hk,hk}
            QFMA16(hA.x, hA.y, hB.x, hB.y, wA.x, wA.y, wB.x, wB.y,
                   Pr, Nr, Pi, Ni, Pj, Nj, Pk, Nk);
        }
        {
            float2 pr = upk2(Pr), nr = upk2(Nr), pi = upk2(Pi), ni = upk2(Ni);
            float2 pj = upk2(Pj), nj = upk2(Nj), pk = upk2(Pk), nk = upk2(Nk);
            float* rb = red + up * 768 + 2 * jp;
            float2 v;
            v.x = pr.x - nr.x; v.y = pr.y - nr.y; *(float2*)(rb)       = v;
            v.x = pi.x - ni.x; v.y = pi.y - ni.y; *(float2*)(rb + 192) = v;
            v.x = pj.x - nj.x; v.y = pj.y - nj.y; *(float2*)(rb + 384) = v;
            v.x = pk.x - nk.x; v.y = pk.y - nk.y; *(float2*)(rb + 576) = v;
        }
        if (t == 383) {
            // frontier poll: keep producers >= 10 steps ahead of consumption
            int tgt = step + 10;
            if (tgt < TT) {
                while (atomicAdd(&g_tdone[tgt], 0u) < 4u) { }
                __threadfence();
            }
        }
        __syncthreads();

        if (t < 256) {
            float gh0 = red[o0]       + red[768 + o0]       + red[1536 + o0]       + red[2304 + o0];
            float gh1 = red[o0 + 64]  + red[768 + o0 + 64]  + red[1536 + o0 + 64]  + red[2304 + o0 + 64];
            float gh2 = red[o0 + 128] + red[768 + o0 + 128] + red[1536 + o0 + 128] + red[2304 + o0 + 128];
            float rg_ = sig_f(gc0 + gh0 + bh0);
            float zg  = sig_f(gc1 + gh1 + bh1);
            float ng  = tanh_f(gc2 + rg_ * (gh2 + bh2));
            hcur = ng + zg * (hcur - ng);
            float2 hd; hd.x = hcur; hd.y = hcur;
            *(float2*)(h4dup + u * 8 + 2 * q) = hd;
            out[((size_t)step * BB + b) * 256 + t] = hcur;
        }
        gc0 = gn0; gc1 = gn1; gc2 = gn2;
        __syncthreads();
    }

    if (t < 256 && out_size >= OUT_MAIN + BB * 256)
        out[OUT_MAIN + b * 256 + t] = hcur;
}

extern "C" void kernel_launch(void* const* d_in, const int* in_sizes, int n_in,
                              void* d_out, int out_size) {
    const float* x    = (const float*)d_in[0];
    const float* hx   = (const float*)d_in[1];
    const float* wihr = (const float*)d_in[2];
    const float* wihi = (const float*)d_in[3];
    const float* wihj = (const float*)d_in[4];
    const float* wihk = (const float*)d_in[5];
    const float* whhr = (const float*)d_in[6];
    const float* whhi = (const float*)d_in[7];
    const float* whhj = (const float*)d_in[8];
    const float* whhk = (const float*)d_in[9];
    const float* bih  = (const float*)d_in[10];
    const float* bhh  = (const float*)d_in[11];
    float* out = (float*)d_out;

    qrn_prep<<<24, 256>>>(wihr, wihi, wihj, wihk, whhr, whhi, whhj, whhk);

    cudaFuncSetAttribute(qrn_fused, cudaFuncAttributeMaxDynamicSharedMemorySize, FUSED_SMEM);
    qrn_fused<<<NCONS + NPROD, 384, FUSED_SMEM>>>(x, bih, hx, bhh, out, out_size);
}